// round 1
// baseline (speedup 1.0000x reference)
#include <cuda_runtime.h>
#include <cuda_bf16.h>

// loss[s] = -(1/496) * [ sum_i x_i*(31-i)                      (linear term, exact)
//                        - sum_{unordered pairs} ln(e_i+e_j)   (pair term, 1 LG2 each)
//                        + 0.0005 * sum_i x_i^2*(31-2i) ]      (beta*l2 term, exact)
// using log_sigmoid(x_i - x_j) == x_i - ln(e^{x_i} + e^{x_j}).

static constexpr int K = 32;
static constexpr float INV_PAIRS = 1.0f / 496.0f;   // K*(K-1)/2
static constexpr float LN2 = 0.69314718055994530942f;

__global__ __launch_bounds__(256)
void rmloss_kernel(const float* __restrict__ logits,
                   float* __restrict__ out,
                   int n_seg)
{
    const int warp = (blockIdx.x * blockDim.x + threadIdx.x) >> 5;
    const int lane = threadIdx.x & 31;
    if (warp >= n_seg) return;

    // Coalesced: one 128B line per warp.
    const float x = logits[warp * K + lane];
    const float e = __expf(x);

    // Per-lane closed-form terms:
    //   linear coeff (K-1-lane), l2 coeff (K-1-2*lane)
    const float cl = (float)(31 - lane);
    const float cq = (float)(31 - 2 * lane);
    float v = x * cl + 0.0005f * (x * x) * cq;   // 0.0005 = 0.5*BETA

    // Pair term: circular offsets 1..15 cover 480 distinct unordered pairs
    // exactly once each; offset 16 covers the remaining 16 pairs twice (weight 0.5).
    float slg = 0.0f;
    #pragma unroll
    for (int o = 1; o <= 15; ++o) {
        float eo = __shfl_sync(0xFFFFFFFFu, e, (lane + o) & 31);
        slg += __log2f(e + eo);
    }
    {
        float eo = __shfl_xor_sync(0xFFFFFFFFu, e, 16);
        slg += 0.5f * __log2f(e + eo);
    }

    v -= LN2 * slg;

    // Warp reduction (butterfly).
    #pragma unroll
    for (int m = 16; m >= 1; m >>= 1)
        v += __shfl_xor_sync(0xFFFFFFFFu, v, m);

    if (lane == 0)
        out[warp] = -v * INV_PAIRS;
}

extern "C" void kernel_launch(void* const* d_in, const int* in_sizes, int n_in,
                              void* d_out, int out_size)
{
    const float* logits = (const float*)d_in[0];
    float* out = (float*)d_out;
    const int n_seg = out_size;              // 32768 segments, one loss each

    const int threads = 256;                 // 8 warps/block -> 8 segments/block
    const int wpb = threads / 32;
    const int blocks = (n_seg + wpb - 1) / wpb;
    rmloss_kernel<<<blocks, threads>>>(logits, out, n_seg);
}